// round 2
// baseline (speedup 1.0000x reference)
#include <cuda_runtime.h>
#include <cuda_bf16.h>
#include <math.h>

// ---------------- problem dims (fixed) ----------------
#define S_ 4
#define K_ 50
#define T_ 25
#define R_ 128
#define V_ 10000
#define TH_ 800
#define EH_ 200
#define B_ 128
#define DELTA_ 0.005

// accumulator slots
#define ACC_KLA 0
#define ACC_KLE 1
#define ACC_KLT 2
#define ACC_NLL 3

// ---------------- device scratch ----------------
__device__ double g_acc[8];
__device__ double g_pst[10];              // ld_p0, ld_pt, d_p0[4], d_pt[4]
__device__ float  g_xpre[T_ * EH_];
__device__ float  g_hseq[T_ * EH_];
__device__ float  g_etas[T_ * K_];
__device__ float  g_h1pre[B_ * TH_];
__device__ float  g_h1[B_ * TH_];
__device__ float  g_h2pre[B_ * TH_];
__device__ float  g_h2[B_ * TH_];
__device__ float  g_mu[B_ * K_];
__device__ float  g_ls[B_ * K_];
__device__ float  g_theta[B_ * K_];
__device__ float  g_alpha0[T_ * K_ * R_];
__device__ float  g_logits[T_ * K_ * V_];   // 50 MB scratch
__device__ float  g_lse[T_ * K_];
__device__ float  g_gates[2][4 * EH_];
__device__ int    g_tcount[T_];
__device__ int    g_tdocs[T_ * B_];
__device__ unsigned g_barc;
__device__ volatile unsigned g_barg;

// ---------------- helpers ----------------
__device__ __forceinline__ float sigf(float x) { return 1.f / (1.f + __expf(-x)); }

__device__ __forceinline__ void gridbar(int nb) {
    __syncthreads();
    if (threadIdx.x == 0) {
        __threadfence();
        unsigned gen = g_barg;
        unsigned arr = atomicAdd(&g_barc, 1u);
        if (arr == (unsigned)(nb - 1)) {
            g_barc = 0;
            __threadfence();
            g_barg = gen + 1;
        } else {
            while (g_barg == gen) { __nanosleep(40); }
            __threadfence();
        }
    }
    __syncthreads();
}

// ---------------- zero accumulators / split-K targets ----------------
__global__ void k_zero() {
    int i = blockIdx.x * blockDim.x + threadIdx.x;
    int stride = gridDim.x * blockDim.x;
    for (int j = i; j < 8; j += stride) g_acc[j] = 0.0;
    for (int j = i; j < T_; j += stride) g_tcount[j] = 0;
    for (int j = i; j < T_ * EH_; j += stride) g_xpre[j] = 0.f;
    for (int j = i; j < B_ * TH_; j += stride) { g_h1pre[j] = 0.f; g_h2pre[j] = 0.f; }
}

// ---------------- prior stats: slogdet + diagonals (4x4, double) ----------------
__global__ void k_pstats(const float* __restrict__ slc) {
    if (threadIdx.x != 0 || blockIdx.x != 0) return;
    double M0[4][4], Mt[4][4];
    for (int i = 0; i < 4; i++)
        for (int j = 0; j < 4; j++) {
            double v = (double)slc[i * 4 + j];
            M0[i][j] = exp(v);
            Mt[i][j] = DELTA_ * v;
        }
    for (int which = 0; which < 2; which++) {
        double lu[4][4];
        for (int i = 0; i < 4; i++)
            for (int j = 0; j < 4; j++) lu[i][j] = which ? Mt[i][j] : M0[i][j];
        double ld = 0.0;
        for (int i = 0; i < 4; i++) {
            int p = i;
            for (int r = i + 1; r < 4; r++)
                if (fabs(lu[r][i]) > fabs(lu[p][i])) p = r;
            if (p != i)
                for (int c = 0; c < 4; c++) { double t = lu[i][c]; lu[i][c] = lu[p][c]; lu[p][c] = t; }
            ld += log(fabs(lu[i][i]));
            for (int r = i + 1; r < 4; r++) {
                double f = lu[r][i] / lu[i][i];
                for (int c = i; c < 4; c++) lu[r][c] -= f * lu[i][c];
            }
        }
        g_pst[which] = ld;
    }
    for (int s = 0; s < 4; s++) {
        g_pst[2 + s] = M0[s][s];
        g_pst[6 + s] = Mt[s][s];
    }
}

// ---------------- alpha0 = mu_q_alpha[0] transposed (K,T,R)->(T,K,R) ----------------
__global__ void k_alpha0(const float* __restrict__ mu) {
    int idx = blockIdx.x * blockDim.x + threadIdx.x;
    if (idx >= T_ * K_ * R_) return;
    int r = idx % R_;
    int k = (idx / R_) % K_;
    int t = idx / (R_ * K_);
    g_alpha0[idx] = mu[(k * T_ + t) * R_ + r];   // s = 0
}

// ---------------- per-time doc lists ----------------
__global__ void k_tlist(const int* __restrict__ times) {
    int b = threadIdx.x;
    if (b >= B_) return;
    int t = times[b];
    int p = atomicAdd(&g_tcount[t], 1);
    g_tdocs[t * B_ + p] = b;
}

// ---------------- kl_alpha ----------------
__global__ void k_klalpha(const float* __restrict__ mu, const float* __restrict__ ls) {
    int idx = blockIdx.x * blockDim.x + threadIdx.x;
    double term = 0.0;
    if (idx < K_ * T_ * R_) {
        int r = idx % R_;
        int t = (idx / R_) % T_;
        int k = idx / (R_ * T_);
        double ldp = (t == 0) ? g_pst[0] : g_pst[1];
        const double* dp = (t == 0) ? (g_pst + 2) : (g_pst + 6);
        double ldq = 0.0, tr = 0.0, quad = 0.0;
        for (int s = 0; s < 4; s++) {
            int off = ((s * K_ + k) * T_ + t) * R_ + r;
            float lsv = ls[off];
            float inv = __expf(-lsv);
            ldq += (double)lsv;
            tr += dp[s] * (double)inv;
            float m = mu[off];
            float d = (t == 0) ? m : (m - mu[off - R_]);
            quad += (double)(d * d) * (double)inv;
        }
        term = ldq - ldp - 4.0 + tr + quad;
    }
    __shared__ double red[256];
    int tid = threadIdx.x;
    red[tid] = term;
    __syncthreads();
    for (int o = 128; o; o >>= 1) {
        if (tid < o) red[tid] += red[tid + o];
        __syncthreads();
    }
    if (tid == 0) atomicAdd(&g_acc[ACC_KLA], red[0]);
}

// ---------------- generic NT GEMM: C[m,n] (+)= sum_k A[m,lda]*B[n,ldb] ----------------
#define GTM 64
#define GTN 64
#define GTK 16
__global__ __launch_bounds__(256) void gemm_nt(const float* __restrict__ A, int lda,
                                               const float* __restrict__ B, int ldb,
                                               float* __restrict__ C,
                                               int M, int N, int K) {
    __shared__ float As[GTK][GTM + 4];
    __shared__ float Bs[GTK][GTN + 4];
    int tid = threadIdx.x;
    int tx = tid & 15, ty = tid >> 4;
    int m0 = blockIdx.x * GTM, n0 = blockIdx.y * GTN;
    int splitK = gridDim.z;
    int kc = (((K + splitK - 1) / splitK) + GTK - 1) & ~(GTK - 1);
    int kbeg = blockIdx.z * kc;
    int kend = min(K, kbeg + kc);
    float acc[4][4] = {};
    for (int k0 = kbeg; k0 < kend; k0 += GTK) {
#pragma unroll
        for (int q = 0; q < 4; q++) {
            int idx = q * 256 + tid;
            int row = idx >> 4, kk = idx & 15;
            int kg = k0 + kk;
            int m = m0 + row;
            As[kk][row] = (m < M && kg < kend) ? A[m * lda + kg] : 0.f;
            int n = n0 + row;
            Bs[kk][row] = (n < N && kg < kend) ? B[n * ldb + kg] : 0.f;
        }
        __syncthreads();
#pragma unroll
        for (int kk = 0; kk < GTK; kk++) {
            float4 a4 = *reinterpret_cast<const float4*>(&As[kk][ty * 4]);
            float4 b4 = *reinterpret_cast<const float4*>(&Bs[kk][tx * 4]);
            float av[4] = {a4.x, a4.y, a4.z, a4.w};
            float bv[4] = {b4.x, b4.y, b4.z, b4.w};
#pragma unroll
            for (int i = 0; i < 4; i++)
#pragma unroll
                for (int j = 0; j < 4; j++) acc[i][j] += av[i] * bv[j];
        }
        __syncthreads();
    }
#pragma unroll
    for (int i = 0; i < 4; i++) {
        int m = m0 + ty * 4 + i;
        if (m >= M) continue;
#pragma unroll
        for (int j = 0; j < 4; j++) {
            int n = n0 + tx * 4 + j;
            if (n >= N) continue;
            if (splitK == 1) C[m * N + n] = acc[i][j];
            else atomicAdd(&C[m * N + n], acc[i][j]);
        }
    }
}

// ---------------- warp-per-output matvec GEMM for small N ----------------
__global__ void matvec_wd(const float* __restrict__ A, int lda,
                          const float* __restrict__ B, int ldb,
                          const float* __restrict__ bias,
                          float* __restrict__ C, int M, int N, int K) {
    int w = (blockIdx.x * blockDim.x + threadIdx.x) >> 5;
    int lane = threadIdx.x & 31;
    int nw = (gridDim.x * blockDim.x) >> 5;
    for (int idx = w; idx < M * N; idx += nw) {
        int m = idx / N, n = idx % N;
        const float* a = A + m * lda;
        const float* b = B + n * ldb;
        float s = 0.f;
        for (int k = lane; k < K; k += 32) s += a[k] * b[k];
        for (int o = 16; o; o >>= 1) s += __shfl_xor_sync(0xffffffffu, s, o);
        if (lane == 0) C[idx] = s + bias[n];
    }
}

// ---------------- LSTM: 16 grid-synced blocks, weights persistent in SMEM ----------------
#define LSTM_NB 16
#define GPB 50   // gates per block (16*50 = 800)
__global__ __launch_bounds__(256) void k_lstm(const float* __restrict__ Wih,
                                              const float* __restrict__ Whh,
                                              const float* __restrict__ bih,
                                              const float* __restrict__ bhh,
                                              const float* __restrict__ emb) {
    extern __shared__ float sm[];
    float* sW = sm;                   // GPB*400
    float* xh = sm + GPB * 400;       // 400: [x(200) | h(200)]
    float* cl = xh + 400;             // 200
    float* bs = cl + 200;             // 64
    int tid = threadIdx.x;
    int blk = blockIdx.x;
    int g0 = blk * GPB;
    for (int i = tid; i < GPB * 200; i += 256) {
        int g = i / 200, e = i % 200;
        sW[g * 400 + e]       = Wih[(g0 + g) * 200 + e];
        sW[g * 400 + 200 + e] = Whh[(g0 + g) * 200 + e];
    }
    for (int i = tid; i < GPB; i += 256) bs[i] = bih[g0 + i] + bhh[g0 + i];
    for (int i = tid; i < 200; i += 256) { xh[200 + i] = 0.f; cl[i] = 0.f; }
    __syncthreads();
    int w = tid >> 5, lane = tid & 31;
    for (int t = 0; t < T_; t++) {
        for (int i = tid; i < 200; i += 256) xh[i] = g_xpre[t * 200 + i] + emb[i];
        __syncthreads();
        volatile float* gbuf = (volatile float*)g_gates[t & 1];
        for (int g = w; g < GPB; g += 8) {
            const float* row = &sW[g * 400];
            float s = 0.f;
            for (int e = lane; e < 400; e += 32) s += row[e] * xh[e];
            for (int o = 16; o; o >>= 1) s += __shfl_xor_sync(0xffffffffu, s, o);
            if (lane == 0) gbuf[g0 + g] = s + bs[g];
        }
        gridbar(LSTM_NB);
        for (int e = tid; e < 200; e += 256) {
            float iv = gbuf[e], fv = gbuf[200 + e], gv = gbuf[400 + e], ov = gbuf[600 + e];
            float c = sigf(fv) * cl[e] + sigf(iv) * tanhf(gv);
            cl[e] = c;
            float h = sigf(ov) * tanhf(c);
            xh[200 + e] = h;
            if (blk == 0) g_hseq[t * 200 + e] = h;
        }
        __syncthreads();
    }
}

// ---------------- eta scan (single block, weights in SMEM) ----------------
__global__ __launch_bounds__(128) void k_eta(const float* __restrict__ Wmu,
                                             const float* __restrict__ bmu,
                                             const float* __restrict__ Wls,
                                             const float* __restrict__ bls) {
    extern __shared__ float sm[];
    float* sWm = sm;                      // 50*250
    float* sWl = sm + 12500;              // 50*250
    float* inp = sm + 25000;              // 256: [h(200) | eta_prev(50)]
    float* mus = sm + 25256;              // 64
    float* lss = sm + 25320;              // 64
    double* red = (double*)(sm + 25384);  // 128 doubles
    int tid = threadIdx.x;
    for (int i = tid; i < 12500; i += 128) { sWm[i] = Wmu[i]; sWl[i] = Wls[i]; }
    for (int i = tid; i < 56; i += 128) inp[200 + i] = 0.f;
    __syncthreads();
    double klacc = 0.0;
    int w = tid >> 5, lane = tid & 31;
    const float LOG_DELTA = logf((float)DELTA_);
    for (int t = 0; t < T_; t++) {
        for (int i = tid; i < 200; i += 128) inp[i] = g_hseq[t * 200 + i];
        __syncthreads();
        for (int o = w; o < 100; o += 4) {
            const float* row = (o < 50) ? &sWm[o * 250] : &sWl[(o - 50) * 250];
            float s = 0.f;
            for (int e = lane; e < 250; e += 32) s += row[e] * inp[e];
            for (int off = 16; off; off >>= 1) s += __shfl_xor_sync(0xffffffffu, s, off);
            if (lane == 0) {
                if (o < 50) mus[o] = s + bmu[o];
                else lss[o - 50] = s + bls[o - 50];
            }
        }
        __syncthreads();
        double kll = 0.0;
        if (tid < 50) {
            float mu = mus[tid], lsv = lss[tid], ep = inp[200 + tid];
            float pls = (t == 0) ? 0.f : LOG_DELTA;
            float den = ((t == 0) ? 1.0f : (float)DELTA_) + 1e-6f;
            float d = mu - ep;
            kll = 0.5 * ((double)((__expf(lsv) + d * d) / den) - 1.0 + (double)pls - (double)lsv);
        }
        red[tid] = kll;
        __syncthreads();
        for (int o = 64; o; o >>= 1) {
            if (tid < o) red[tid] += red[tid + o];
            __syncthreads();
        }
        if (tid == 0) klacc += red[0];
        __syncthreads();
        if (tid < 50) { inp[200 + tid] = mus[tid]; g_etas[t * 50 + tid] = mus[tid]; }
        __syncthreads();
    }
    if (tid == 0) atomicAdd(&g_acc[ACC_KLE], klacc);
}

// ---------------- activation 1: add eta part + bias + tanh ----------------
__global__ void k_act1(const float* __restrict__ b1, const float* __restrict__ W1,
                       const int* __restrict__ times) {
    int idx = blockIdx.x * blockDim.x + threadIdx.x;
    if (idx >= B_ * TH_) return;
    int b = idx / TH_, j = idx % TH_;
    float v = g_h1pre[idx] + b1[j];
    const float* e = g_etas + times[b] * K_;
    const float* wtail = W1 + j * (V_ + K_) + V_;
#pragma unroll 10
    for (int k = 0; k < K_; k++) v += e[k] * wtail[k];
    g_h1[idx] = tanhf(v);
}

// ---------------- activation 2 ----------------
__global__ void k_act2(const float* __restrict__ b2) {
    int idx = blockIdx.x * blockDim.x + threadIdx.x;
    if (idx >= B_ * TH_) return;
    g_h2[idx] = tanhf(g_h2pre[idx] + b2[idx % TH_]);
}

// ---------------- theta softmax + kl_theta ----------------
__global__ __launch_bounds__(64) void k_theta(const int* __restrict__ times) {
    int b = blockIdx.x, tid = threadIdx.x;
    __shared__ float sf[64];
    __shared__ double sd[64];
    float m = (tid < K_) ? g_mu[b * K_ + tid] : -1e30f;
    sf[tid] = m;
    __syncthreads();
    for (int o = 32; o; o >>= 1) { if (tid < o) sf[tid] = fmaxf(sf[tid], sf[tid + o]); __syncthreads(); }
    float mx = sf[0];
    __syncthreads();
    float e = (tid < K_) ? __expf(m - mx) : 0.f;
    sf[tid] = e;
    __syncthreads();
    for (int o = 32; o; o >>= 1) { if (tid < o) sf[tid] += sf[tid + o]; __syncthreads(); }
    float sum = sf[0];
    if (tid < K_) g_theta[b * K_ + tid] = e / sum;
    double kl = 0.0;
    if (tid < K_) {
        float lsv = g_ls[b * K_ + tid];
        float et = g_etas[times[b] * K_ + tid];
        float d = m - et;
        kl = 0.5 * ((double)((__expf(lsv) + d * d) / (1.0f + 1e-6f)) - 1.0 - (double)lsv);
    }
    sd[tid] = kl;
    __syncthreads();
    for (int o = 32; o; o >>= 1) { if (tid < o) sd[tid] += sd[tid + o]; __syncthreads(); }
    if (tid == 0) atomicAdd(&g_acc[ACC_KLT], sd[0]);
}

// ---------------- per-row log-sum-exp over V ----------------
__global__ __launch_bounds__(256) void k_lse() {
    int row = blockIdx.x;
    int tid = threadIdx.x;
    const float* p = g_logits + row * V_;
    __shared__ float sf[256];
    float mx = -1e30f;
    for (int v = tid; v < V_; v += 256) mx = fmaxf(mx, p[v]);
    sf[tid] = mx;
    __syncthreads();
    for (int o = 128; o; o >>= 1) { if (tid < o) sf[tid] = fmaxf(sf[tid], sf[tid + o]); __syncthreads(); }
    mx = sf[0];
    __syncthreads();
    float s = 0.f;
    for (int v = tid; v < V_; v += 256) s += __expf(p[v] - mx);
    sf[tid] = s;
    __syncthreads();
    for (int o = 128; o; o >>= 1) { if (tid < o) sf[tid] += sf[tid + o]; __syncthreads(); }
    if (tid == 0) g_lse[row] = mx + logf(sf[0]);
}

// ---------------- mix + nll, grouped by time ----------------
#define VC 500
__global__ __launch_bounds__(512) void k_mix(const float* __restrict__ bows) {
    int t = blockIdx.x;
    int tid = threadIdx.x;
    int v = blockIdx.y * VC + tid;
    bool act = (tid < VC);
    int n_t = g_tcount[t];
    __shared__ float lse_s[K_];
    __shared__ float thg[8][K_];
    __shared__ double red[512];
    if (tid < K_) lse_s[tid] = g_lse[t * K_ + tid];
    double nllpart = 0.0;
    for (int grp = 0; grp < n_t; grp += 8) {
        int gn = min(8, n_t - grp);
        __syncthreads();
        if (tid < 8 * K_) {
            int g = tid / K_, k = tid % K_;
            thg[g][k] = (g < gn) ? g_theta[g_tdocs[t * B_ + grp + g] * K_ + k] : 0.f;
        }
        __syncthreads();
        if (act) {
            float a[8] = {0, 0, 0, 0, 0, 0, 0, 0};
            const float* lrow = g_logits + (t * K_) * V_ + v;
            for (int k = 0; k < K_; k++) {
                float ev = __expf(lrow[k * V_] - lse_s[k]);
#pragma unroll
                for (int g = 0; g < 8; g++) a[g] += thg[g][k] * ev;
            }
            for (int g = 0; g < gn; g++) {
                int d = g_tdocs[t * B_ + grp + g];
                nllpart -= (double)(logf(a[g] + 1e-6f) * bows[d * V_ + v]);
            }
        }
    }
    red[tid] = nllpart;
    __syncthreads();
    for (int o = 256; o; o >>= 1) {
        if (tid < o) red[tid] += red[tid + o];
        __syncthreads();
    }
    if (tid == 0) atomicAdd(&g_acc[ACC_NLL], red[0]);
}

// ---------------- final combine ----------------
__global__ void k_final(const int* __restrict__ nd, float* __restrict__ out, int out_size) {
    if (threadIdx.x != 0 || blockIdx.x != 0) return;
    double coeff = (double)nd[0] / (double)B_;
    double nll_s = g_acc[ACC_NLL] * coeff;
    double kth   = g_acc[ACC_KLT] * coeff;
    double kla   = g_acc[ACC_KLA];
    double kle   = g_acc[ACC_KLE];
    double nelbo = nll_s + kla + kle + kth;
    double vals[5] = {nelbo, nll_s, kla, kle, kth};
    for (int i = 0; i < 5 && i < out_size; i++) out[i] = (float)vals[i];
}

// ---------------- host launcher ----------------
extern "C" void kernel_launch(void* const* d_in, const int* in_sizes, int n_in,
                              void* d_out, int out_size) {
    const float* mu_q  = (const float*)d_in[0];
    const float* lsq   = (const float*)d_in[1];
    const float* slc   = (const float*)d_in[2];
    const float* rho   = (const float*)d_in[3];
    const float* W1    = (const float*)d_in[4];
    const float* b1    = (const float*)d_in[5];
    const float* W2    = (const float*)d_in[6];
    const float* b2    = (const float*)d_in[7];
    const float* muW   = (const float*)d_in[8];
    const float* mub   = (const float*)d_in[9];
    const float* lsW   = (const float*)d_in[10];
    const float* lsb   = (const float*)d_in[11];
    const float* emW   = (const float*)d_in[12];
    const float* emb   = (const float*)d_in[13];
    const float* Wih   = (const float*)d_in[14];
    const float* Whh   = (const float*)d_in[15];
    const float* bih   = (const float*)d_in[16];
    const float* bhh   = (const float*)d_in[17];
    const float* Wme   = (const float*)d_in[18];
    const float* bme   = (const float*)d_in[19];
    const float* Wle   = (const float*)d_in[20];
    const float* ble   = (const float*)d_in[21];
    const float* bows  = (const float*)d_in[22];
    const float* nbows = (const float*)d_in[23];
    const float* rnn   = (const float*)d_in[24];
    const int*   times = (const int*)d_in[25];
    const int*   ndocs = (const int*)d_in[26];
    float* out = (float*)d_out;

    float *p_xpre, *p_h1pre, *p_h1, *p_h2pre, *p_h2, *p_mu, *p_ls, *p_alpha0, *p_logits;
    cudaGetSymbolAddress((void**)&p_xpre,   g_xpre);
    cudaGetSymbolAddress((void**)&p_h1pre,  g_h1pre);
    cudaGetSymbolAddress((void**)&p_h1,     g_h1);
    cudaGetSymbolAddress((void**)&p_h2pre,  g_h2pre);
    cudaGetSymbolAddress((void**)&p_h2,     g_h2);
    cudaGetSymbolAddress((void**)&p_mu,     g_mu);
    cudaGetSymbolAddress((void**)&p_ls,     g_ls);
    cudaGetSymbolAddress((void**)&p_alpha0, g_alpha0);
    cudaGetSymbolAddress((void**)&p_logits, g_logits);

    const int LSTM_SMEM = (GPB * 400 + 400 + 200 + 64) * 4;                 // ~82.7 KB
    const int ETA_SMEM  = 25384 * 4 + 128 * 8;                              // ~102.6 KB
    cudaFuncSetAttribute(k_lstm, cudaFuncAttributeMaxDynamicSharedMemorySize, LSTM_SMEM);
    cudaFuncSetAttribute(k_eta,  cudaFuncAttributeMaxDynamicSharedMemorySize, ETA_SMEM);

    // 0. zero accumulators + split-K targets
    k_zero<<<64, 256>>>();
    // 1. prior stats, alpha0 pack, doc lists
    k_pstats<<<1, 32>>>(slc);
    k_alpha0<<<(T_ * K_ * R_ + 255) / 256, 256>>>(mu_q);
    k_tlist<<<1, 128>>>(times);
    // 2. kl_alpha
    k_klalpha<<<(K_ * T_ * R_ + 255) / 256, 256>>>(mu_q, lsq);
    // 3. xpre = rnn_inp @ eta_map_W^T   (25x200, K=10000)
    gemm_nt<<<dim3(1, 4, 16), 256>>>(rnn, V_, emW, V_, p_xpre, T_, EH_, V_);
    // 4. LSTM over 25 steps (16 grid-synced blocks)
    k_lstm<<<LSTM_NB, 256, LSTM_SMEM>>>(Wih, Whh, bih, bhh, emb);
    // 5. eta scan
    k_eta<<<1, 128, ETA_SMEM>>>(Wme, bme, Wle, ble);
    // 6. theta MLP
    gemm_nt<<<dim3(2, 13, 8), 256>>>(nbows, V_, W1, V_ + K_, p_h1pre, B_, TH_, V_);
    k_act1<<<(B_ * TH_ + 255) / 256, 256>>>(b1, W1, times);
    gemm_nt<<<dim3(2, 13, 8), 256>>>(p_h1, TH_, W2, TH_, p_h2pre, B_, TH_, TH_);
    k_act2<<<(B_ * TH_ + 255) / 256, 256>>>(b2);
    matvec_wd<<<50, 256>>>(p_h2, TH_, muW, TH_, mub, p_mu, B_, K_, TH_);
    matvec_wd<<<50, 256>>>(p_h2, TH_, lsW, TH_, lsb, p_ls, B_, K_, TH_);
    k_theta<<<B_, 64>>>(times);
    // 7. beta logits: (T*K, V) = alpha0 (T*K,128) @ rho^T (V,128)
    gemm_nt<<<dim3(20, 157, 1), 256>>>(p_alpha0, R_, rho, R_, p_logits, T_ * K_, V_, R_);
    k_lse<<<T_ * K_, 256>>>();
    // 8. mix + nll
    k_mix<<<dim3(T_, V_ / VC), 512>>>(bows);
    // 9. combine
    k_final<<<1, 1>>>(ndocs, out, out_size);
}